// round 7
// baseline (speedup 1.0000x reference)
#include <cuda_runtime.h>

// gnn_42460046688469 — Fourier-graph gather + complex weighted aggregate + permuted scatter.
//
// R7 = R6 winner + PARALLEL DETECTION.
// R6 profile showed detect_kernel at 47.6us: one warp, ~200 serial dependent
// DRAM probes at MLP=1 (~600-1000 cy each). Same probes now issue from 256
// threads concurrently (two dependent memory rounds total) and reduce via
// shared atomics -> ~3us. Decisions and sample positions are unchanged.
//
// R6 core (kept): per-launch repack of Xf_real/Xf_imag into an interleaved-
// complex __device__ scratch (128B = one full L2 line per row), then all
// gathers touch exactly one fully-used line. Content-based interface
// detection; every gathered index clamped; output layout chosen from
// out_size; all stores bounded.

#define K_NB 8

struct Cfg { int u; int is64; int niSel; int imagFirst; };
__device__ Cfg g_cfg;

// Interleaved-complex Xf table: up to 1,048,576 rows x 8 float4 (134 MB).
__device__ __align__(16) float4 g_scratch[8388608];

__global__ void detect_kernel(const unsigned* __restrict__ m0,
                              const unsigned* __restrict__ m1,
                              const unsigned* __restrict__ m2,
                              const unsigned* __restrict__ hind,
                              int s_mid, int s_hi)
{
    __shared__ int sOk[3];
    __shared__ int sZeros;
    __shared__ unsigned sVmax;
    __shared__ int sIs64;

    int tid = threadIdx.x;
    if (tid < 3) sOk[tid] = 1;
    if (tid == 3) sZeros = 0;
    if (tid == 4) sVmax = 0u;
    __syncthreads();

    int Wm = s_mid >> 2;   // words provably in-bounds under both unit schemes
    int Wh = s_hi >> 2;

    // Round 1 (parallel): NI-content probes + int64 probes.
    if (tid < 192) {
        int b = tid >> 6;            // buffer 0..2
        int j = tid & 63;            // sample 0..63
        int step = Wm / 67; if (step < 1) step = 1;
        const unsigned* ms = (b == 0) ? m0 : (b == 1) ? m1 : m2;
        unsigned v = ms[(j * step + j) % Wm];
        if (v >= 0x01000000u) atomicExch(&sOk[b], 0);
    } else {
        int j = tid - 192;           // sample 0..63
        int step = Wh / 67; if (step < 1) step = 1;
        int w = ((j * step + j) % Wh) | 1;
        if (hind[w] == 0u) atomicAdd(&sZeros, 1);
    }
    __syncthreads();
    if (tid == 0) sIs64 = (sZeros >= 48) ? 1 : 0;
    __syncthreads();

    // Round 2 (parallel, depends on is64): units probe (vmax of hier_ind).
    if (tid >= 192) {
        int j = tid - 192;
        int step = Wh / 67; if (step < 1) step = 1;
        int w = (j * step + j) % Wh;
        if (sIs64) w &= ~1;          // low (value) word of int64
        atomicMax(&sVmax, hind[w]);
    }
    __syncthreads();

    if (tid == 0) {
        int niSel = 2;
        if (sOk[0] && !sOk[2]) niSel = 0;
        else if (sOk[1] && !sOk[0] && !sOk[2]) niSel = 1;
        int imagFirst = (niSel == 0) ? 1 : 0;

        unsigned thresh = sIs64 ? (unsigned)(s_hi >> 3) : (unsigned)(s_hi >> 2);
        int u = (sVmax >= thresh) ? 1 : 4;

        Cfg c; c.u = u; c.is64 = sIs64; c.niSel = niSel; c.imagFirst = imagFirst;
        g_cfg = c;
    }
}

// Streaming repack: Xf_real/Xf_imag (split) -> interleaved complex rows.
__global__ void __launch_bounds__(256) repack_kernel(
    const float* __restrict__ xf0, const float* __restrict__ xf1, int s_max)
{
    Cfg c = g_cfg;
    int Mrows = (s_max / c.u) / 16;
    int i = blockIdx.x * blockDim.x + threadIdx.x;
    if (i >= Mrows * 4) return;

    const float4* R = (const float4*)(c.imagFirst ? xf1 : xf0);
    const float4* I = (const float4*)(c.imagFirst ? xf0 : xf1);
    float4 xr = __ldg(R + i);
    float4 xi = __ldg(I + i);
    g_scratch[i * 2]     = make_float4(xr.x, xi.x, xr.y, xi.y);
    g_scratch[i * 2 + 1] = make_float4(xr.z, xi.z, xr.w, xi.w);
}

__device__ __forceinline__ int load_idx(const void* p, int off, int is64) {
    return is64 ? (int)((const long long*)p)[off] : ((const int*)p)[off];
}

__global__ void __launch_bounds__(256, 8) gnn_fourier_kernel(
    const void*  __restrict__ m0,  const void*  __restrict__ m1,
    const void*  __restrict__ m2,
    const void*  __restrict__ hmask, const void* __restrict__ hind,
    float4* __restrict__ out,
    int s_max, int s_mid, int s_hi, int s_hm, int out_count)
{
    Cfg c = g_cfg;

    int idxDiv = c.u * ((c.is64 && c.u == 4) ? 2 : 1);
    int NH     = s_hi / idxDiv;
    int H      = s_hm / idxDiv;
    int N      = (s_mid / c.u) / K_NB;
    int Mrows  = (s_max / c.u) / 16;

    int gid = blockIdx.x * blockDim.x + threadIdx.x;
    int row = gid >> 2;
    if (row >= NH) return;
    int t = gid & 3;

    const void* mids[3] = { m0, m1, m2 };
    const void* NIp = mids[c.niSel];
    const void* wa  = (c.niSel == 0) ? m1 : m0;
    const void* wb  = (c.niSel == 2) ? m1 : m2;
    const float* wR = (const float*)(c.imagFirst ? wb : wa);
    const float* wI = (const float*)(c.imagFirst ? wa : wb);

    unsigned src = (unsigned)load_idx(hind, row, c.is64);
    src = min(src, (unsigned)(NH - 1));

    const float4* S = g_scratch;
    float4 a0, a1;   // interleaved (re,im) accumulators: channels [4t, 4t+4)

    if ((int)src < N) {
        a0 = make_float4(0.f, 0.f, 0.f, 0.f);
        a1 = make_float4(0.f, 0.f, 0.f, 0.f);
        #pragma unroll
        for (int k = 0; k < K_NB; ++k) {
            int off = k * N + (int)src;
            unsigned idx = (unsigned)load_idx(NIp, off, c.is64);
            idx = min(idx, (unsigned)(Mrows - 1));
            float wr = __ldg(wR + off);
            float wi = __ldg(wI + off);
            long long base = (long long)idx * 8 + t * 2;
            float4 v0 = __ldg(S + base);
            float4 v1 = __ldg(S + base + 1);
            a0.x = fmaf(wr, v0.x, fmaf(-wi, v0.y, a0.x));
            a0.y = fmaf(wr, v0.y, fmaf( wi, v0.x, a0.y));
            a0.z = fmaf(wr, v0.z, fmaf(-wi, v0.w, a0.z));
            a0.w = fmaf(wr, v0.w, fmaf( wi, v0.z, a0.w));
            a1.x = fmaf(wr, v1.x, fmaf(-wi, v1.y, a1.x));
            a1.y = fmaf(wr, v1.y, fmaf( wi, v1.x, a1.y));
            a1.z = fmaf(wr, v1.z, fmaf(-wi, v1.w, a1.z));
            a1.w = fmaf(wr, v1.w, fmaf( wi, v1.z, a1.w));
        }
    } else {
        unsigned hoff = min((unsigned)((int)src - N), (unsigned)(H - 1));
        unsigned idx = (unsigned)load_idx(hmask, (int)hoff, c.is64);
        idx = min(idx, (unsigned)(Mrows - 1));
        long long base = (long long)idx * 8 + t * 2;
        a0 = __ldg(S + base);
        a1 = __ldg(S + base + 1);
    }

    long long needF = (long long)NH * 32;
    int maxF4 = out_count >> 2;

    if ((long long)out_count >= needF) {
        int ob = row * 8 + t * 2;
        if (ob + 1 < maxF4) {
            out[ob]     = a0;
            out[ob + 1] = a1;
        }
    } else {
        int ob = row * 4 + t;
        if (ob < maxF4) out[ob] = make_float4(a0.x, a0.z, a1.x, a1.z);
    }
}

extern "C" void kernel_launch(void* const* d_in, const int* in_sizes, int n_in,
                              void* d_out, int out_size) {
    int smax = 0;
    for (int i = 0; i < n_in; ++i) if (in_sizes[i] > smax) smax = in_sizes[i];

    int smid = 0;
    for (int i = 0; i < n_in && !smid; ++i) {
        int s = in_sizes[i];
        if (s == smax || s <= 64) continue;
        int cnt = 0;
        for (int j = 0; j < n_in; ++j) if (in_sizes[j] == s) cnt++;
        if (cnt == 3) smid = s;
    }

    const float* xf[2] = { 0, 0 }; int nx = 0;
    const void*  mid[3] = { 0, 0, 0 }; int nm = 0;
    int hiPos = -1, hmPos = -1;
    if (smid) {
        for (int i = 0; i < n_in; ++i) {
            int s = in_sizes[i];
            if (s == smax)      { if (nx < 2) xf[nx++] = (const float*)d_in[i]; }
            else if (s == smid) { if (nm < 3) mid[nm++] = d_in[i]; }
            else if (s > 64) {
                if (hiPos < 0) hiPos = i;
                else if (s > in_sizes[hiPos]) { hmPos = hiPos; hiPos = i; }
                else hmPos = i;
            }
        }
    } else {
        int s2 = 0;
        for (int i = 0; i < n_in && !s2; ++i) {
            int s = in_sizes[i];
            if (s == smax || s <= 64) continue;
            int cnt = 0;
            for (int j = 0; j < n_in; ++j) if (in_sizes[j] == s) cnt++;
            if (cnt == 2) s2 = s;
        }
        smid = s2;
        int niPos = -1;
        for (int i = 0; i < n_in; ++i) if (in_sizes[i] == 2 * s2) niPos = i;
        int order[3], no = 0;
        for (int i = 0; i < n_in && no < 3; ++i)
            if (in_sizes[i] == s2 || i == niPos) order[no++] = i;
        for (int q = 0; q < 3; ++q) mid[q] = d_in[order[q]];
        for (int i = 0; i < n_in; ++i) {
            int s = in_sizes[i];
            if (s == smax) { if (nx < 2) xf[nx++] = (const float*)d_in[i]; }
            else if (s > 64 && s != s2 && i != niPos) {
                if (hiPos < 0) hiPos = i;
                else if (s > in_sizes[hiPos]) { hmPos = hiPos; hiPos = i; }
                else hmPos = i;
            }
        }
    }

    int s_hi = in_sizes[hiPos];
    int s_hm = in_sizes[hmPos];

    detect_kernel<<<1, 256>>>((const unsigned*)mid[0], (const unsigned*)mid[1],
                              (const unsigned*)mid[2], (const unsigned*)d_in[hiPos],
                              smid, s_hi);

    {
        long long rthreads = (long long)smax / 4;
        int block = 256;
        long long rgrid = (rthreads + block - 1) / block;
        repack_kernel<<<(int)rgrid, block>>>(xf[0], xf[1], smax);
    }

    long long rows_max = s_hi;   // worst case; excess threads exit
    long long total_threads = rows_max * 4;
    int block = 256;
    long long grid = (total_threads + block - 1) / block;

    gnn_fourier_kernel<<<(int)grid, block>>>(mid[0], mid[1], mid[2],
                                             d_in[hmPos], d_in[hiPos],
                                             (float4*)d_out,
                                             smax, smid, s_hi, s_hm, out_size);
}

// round 8
// speedup vs baseline: 1.4055x; 1.4055x over previous
#include <cuda_runtime.h>
#include <cuda_fp16.h>

// gnn_42460046688469 — Fourier-graph gather + complex weighted aggregate + permuted scatter.
//
// R8 = R7 + FP16 SCRATCH TABLE (L2-RESIDENT GATHERS).
// The fp32 interleaved table (134 MB) exceeds L2 (126 MB) and the use-once
// streams (~184 MB) thrash it, so the 536 MB of logical gather traffic kept
// spilling to DRAM. The repacked table now stores (re,im) as __half2:
// 64 B/row, 67 MB total -> resident in L2 alongside the streams. Weights,
// accumulation and output remain fp32 (expected rel_err ~3e-4 < 1e-3).
// Parallel detection (R7, 6.6us) kept. Repack shrinks to 201 MB of traffic.
//
// Interface handling (proven R4-R7): content-based detection of operand
// order / index width / size units; every gathered index clamped; output
// layout chosen from out_size; all stores bounded.

#define K_NB 8

struct Cfg { int u; int is64; int niSel; int imagFirst; };
__device__ Cfg g_cfg;

// Interleaved fp16 complex table: up to 1,048,576 rows x 64 B (67 MB).
__device__ __align__(16) uint4 g_scratch[4194304];

__global__ void detect_kernel(const unsigned* __restrict__ m0,
                              const unsigned* __restrict__ m1,
                              const unsigned* __restrict__ m2,
                              const unsigned* __restrict__ hind,
                              int s_mid, int s_hi)
{
    __shared__ int sOk[3];
    __shared__ int sZeros;
    __shared__ unsigned sVmax;
    __shared__ int sIs64;

    int tid = threadIdx.x;
    if (tid < 3) sOk[tid] = 1;
    if (tid == 3) sZeros = 0;
    if (tid == 4) sVmax = 0u;
    __syncthreads();

    int Wm = s_mid >> 2;   // words provably in-bounds under both unit schemes
    int Wh = s_hi >> 2;

    if (tid < 192) {
        int b = tid >> 6;
        int j = tid & 63;
        int step = Wm / 67; if (step < 1) step = 1;
        const unsigned* ms = (b == 0) ? m0 : (b == 1) ? m1 : m2;
        unsigned v = ms[(j * step + j) % Wm];
        if (v >= 0x01000000u) atomicExch(&sOk[b], 0);
    } else {
        int j = tid - 192;
        int step = Wh / 67; if (step < 1) step = 1;
        int w = ((j * step + j) % Wh) | 1;
        if (hind[w] == 0u) atomicAdd(&sZeros, 1);
    }
    __syncthreads();
    if (tid == 0) sIs64 = (sZeros >= 48) ? 1 : 0;
    __syncthreads();

    if (tid >= 192) {
        int j = tid - 192;
        int step = Wh / 67; if (step < 1) step = 1;
        int w = (j * step + j) % Wh;
        if (sIs64) w &= ~1;
        atomicMax(&sVmax, hind[w]);
    }
    __syncthreads();

    if (tid == 0) {
        int niSel = 2;
        if (sOk[0] && !sOk[2]) niSel = 0;
        else if (sOk[1] && !sOk[0] && !sOk[2]) niSel = 1;
        int imagFirst = (niSel == 0) ? 1 : 0;

        unsigned thresh = sIs64 ? (unsigned)(s_hi >> 3) : (unsigned)(s_hi >> 2);
        int u = (sVmax >= thresh) ? 1 : 4;

        Cfg c; c.u = u; c.is64 = sIs64; c.niSel = niSel; c.imagFirst = imagFirst;
        g_cfg = c;
    }
}

// Streaming repack: split fp32 Xf_real/Xf_imag -> interleaved __half2 rows.
// Thread i handles 4 channels of one row: reads 2x16B fp32, writes 16B fp16.
__global__ void __launch_bounds__(256) repack_kernel(
    const float* __restrict__ xf0, const float* __restrict__ xf1, int s_max)
{
    Cfg c = g_cfg;
    int Mrows = (s_max / c.u) / 16;
    int i = blockIdx.x * blockDim.x + threadIdx.x;
    if (i >= Mrows * 4) return;

    const float4* R = (const float4*)(c.imagFirst ? xf1 : xf0);
    const float4* I = (const float4*)(c.imagFirst ? xf0 : xf1);
    float4 xr = __ldg(R + i);
    float4 xi = __ldg(I + i);

    __half2 h0 = __floats2half2_rn(xr.x, xi.x);
    __half2 h1 = __floats2half2_rn(xr.y, xi.y);
    __half2 h2 = __floats2half2_rn(xr.z, xi.z);
    __half2 h3 = __floats2half2_rn(xr.w, xi.w);

    uint4 o;
    o.x = *reinterpret_cast<unsigned*>(&h0);
    o.y = *reinterpret_cast<unsigned*>(&h1);
    o.z = *reinterpret_cast<unsigned*>(&h2);
    o.w = *reinterpret_cast<unsigned*>(&h3);
    g_scratch[i] = o;
}

__device__ __forceinline__ int load_idx(const void* p, int off, int is64) {
    return is64 ? (int)((const long long*)p)[off] : ((const int*)p)[off];
}

__device__ __forceinline__ float2 h2f(unsigned u) {
    __half2 h = *reinterpret_cast<__half2*>(&u);
    return __half22float2(h);
}

__global__ void __launch_bounds__(256, 8) gnn_fourier_kernel(
    const void*  __restrict__ m0,  const void*  __restrict__ m1,
    const void*  __restrict__ m2,
    const void*  __restrict__ hmask, const void* __restrict__ hind,
    float4* __restrict__ out,
    int s_max, int s_mid, int s_hi, int s_hm, int out_count)
{
    Cfg c = g_cfg;

    int idxDiv = c.u * ((c.is64 && c.u == 4) ? 2 : 1);
    int NH     = s_hi / idxDiv;
    int H      = s_hm / idxDiv;
    int N      = (s_mid / c.u) / K_NB;
    int Mrows  = (s_max / c.u) / 16;

    int gid = blockIdx.x * blockDim.x + threadIdx.x;
    int row = gid >> 2;
    if (row >= NH) return;
    int t = gid & 3;

    const void* mids[3] = { m0, m1, m2 };
    const void* NIp = mids[c.niSel];
    const void* wa  = (c.niSel == 0) ? m1 : m0;
    const void* wb  = (c.niSel == 2) ? m1 : m2;
    const float* wR = (const float*)(c.imagFirst ? wb : wa);
    const float* wI = (const float*)(c.imagFirst ? wa : wb);

    unsigned src = (unsigned)load_idx(hind, row, c.is64);
    src = min(src, (unsigned)(NH - 1));

    const uint4* S = g_scratch;
    float4 a0, a1;   // interleaved (re,im) accumulators: channels [4t, 4t+4)

    if ((int)src < N) {
        a0 = make_float4(0.f, 0.f, 0.f, 0.f);
        a1 = make_float4(0.f, 0.f, 0.f, 0.f);
        #pragma unroll
        for (int k = 0; k < K_NB; ++k) {
            int off = k * N + (int)src;
            unsigned idx = (unsigned)load_idx(NIp, off, c.is64);
            idx = min(idx, (unsigned)(Mrows - 1));
            float wr = __ldg(wR + off);
            float wi = __ldg(wI + off);
            uint4 v = __ldg(S + (long long)idx * 4 + t);   // 16B: 4 channels fp16 (re,im)
            float2 f0 = h2f(v.x), f1 = h2f(v.y), f2 = h2f(v.z), f3 = h2f(v.w);
            a0.x = fmaf(wr, f0.x, fmaf(-wi, f0.y, a0.x));
            a0.y = fmaf(wr, f0.y, fmaf( wi, f0.x, a0.y));
            a0.z = fmaf(wr, f1.x, fmaf(-wi, f1.y, a0.z));
            a0.w = fmaf(wr, f1.y, fmaf( wi, f1.x, a0.w));
            a1.x = fmaf(wr, f2.x, fmaf(-wi, f2.y, a1.x));
            a1.y = fmaf(wr, f2.y, fmaf( wi, f2.x, a1.y));
            a1.z = fmaf(wr, f3.x, fmaf(-wi, f3.y, a1.z));
            a1.w = fmaf(wr, f3.y, fmaf( wi, f3.x, a1.w));
        }
    } else {
        unsigned hoff = min((unsigned)((int)src - N), (unsigned)(H - 1));
        unsigned idx = (unsigned)load_idx(hmask, (int)hoff, c.is64);
        idx = min(idx, (unsigned)(Mrows - 1));
        uint4 v = __ldg(S + (long long)idx * 4 + t);
        float2 f0 = h2f(v.x), f1 = h2f(v.y), f2 = h2f(v.z), f3 = h2f(v.w);
        a0 = make_float4(f0.x, f0.y, f1.x, f1.y);
        a1 = make_float4(f2.x, f2.y, f3.x, f3.y);
    }

    long long needF = (long long)NH * 32;
    int maxF4 = out_count >> 2;

    if ((long long)out_count >= needF) {
        int ob = row * 8 + t * 2;
        if (ob + 1 < maxF4) {
            out[ob]     = a0;
            out[ob + 1] = a1;
        }
    } else {
        int ob = row * 4 + t;
        if (ob < maxF4) out[ob] = make_float4(a0.x, a0.z, a1.x, a1.z);
    }
}

extern "C" void kernel_launch(void* const* d_in, const int* in_sizes, int n_in,
                              void* d_out, int out_size) {
    int smax = 0;
    for (int i = 0; i < n_in; ++i) if (in_sizes[i] > smax) smax = in_sizes[i];

    int smid = 0;
    for (int i = 0; i < n_in && !smid; ++i) {
        int s = in_sizes[i];
        if (s == smax || s <= 64) continue;
        int cnt = 0;
        for (int j = 0; j < n_in; ++j) if (in_sizes[j] == s) cnt++;
        if (cnt == 3) smid = s;
    }

    const float* xf[2] = { 0, 0 }; int nx = 0;
    const void*  mid[3] = { 0, 0, 0 }; int nm = 0;
    int hiPos = -1, hmPos = -1;
    if (smid) {
        for (int i = 0; i < n_in; ++i) {
            int s = in_sizes[i];
            if (s == smax)      { if (nx < 2) xf[nx++] = (const float*)d_in[i]; }
            else if (s == smid) { if (nm < 3) mid[nm++] = d_in[i]; }
            else if (s > 64) {
                if (hiPos < 0) hiPos = i;
                else if (s > in_sizes[hiPos]) { hmPos = hiPos; hiPos = i; }
                else hmPos = i;
            }
        }
    } else {
        int s2 = 0;
        for (int i = 0; i < n_in && !s2; ++i) {
            int s = in_sizes[i];
            if (s == smax || s <= 64) continue;
            int cnt = 0;
            for (int j = 0; j < n_in; ++j) if (in_sizes[j] == s) cnt++;
            if (cnt == 2) s2 = s;
        }
        smid = s2;
        int niPos = -1;
        for (int i = 0; i < n_in; ++i) if (in_sizes[i] == 2 * s2) niPos = i;
        int order[3], no = 0;
        for (int i = 0; i < n_in && no < 3; ++i)
            if (in_sizes[i] == s2 || i == niPos) order[no++] = i;
        for (int q = 0; q < 3; ++q) mid[q] = d_in[order[q]];
        for (int i = 0; i < n_in; ++i) {
            int s = in_sizes[i];
            if (s == smax) { if (nx < 2) xf[nx++] = (const float*)d_in[i]; }
            else if (s > 64 && s != s2 && i != niPos) {
                if (hiPos < 0) hiPos = i;
                else if (s > in_sizes[hiPos]) { hmPos = hiPos; hiPos = i; }
                else hmPos = i;
            }
        }
    }

    int s_hi = in_sizes[hiPos];
    int s_hm = in_sizes[hmPos];

    detect_kernel<<<1, 256>>>((const unsigned*)mid[0], (const unsigned*)mid[1],
                              (const unsigned*)mid[2], (const unsigned*)d_in[hiPos],
                              smid, s_hi);

    {
        long long rthreads = (long long)smax / 4;
        int block = 256;
        long long rgrid = (rthreads + block - 1) / block;
        repack_kernel<<<(int)rgrid, block>>>(xf[0], xf[1], smax);
    }

    long long rows_max = s_hi;   // worst case; excess threads exit
    long long total_threads = rows_max * 4;
    int block = 256;
    long long grid = (total_threads + block - 1) / block;

    gnn_fourier_kernel<<<(int)grid, block>>>(mid[0], mid[1], mid[2],
                                             d_in[hmPos], d_in[hiPos],
                                             (float4*)d_out,
                                             smax, smid, s_hi, s_hm, out_size);
}